// round 2
// baseline (speedup 1.0000x reference)
#include <cuda_runtime.h>

#define HEADS 32
#define SEQ   2048
#define D     64
#define F     128           // 2*D hedgehog feature dim
#define ROWS  (HEADS*SEQ)   // 65536

#define WS 65               // smem stride for 64-wide rows (conflict pad)
#define FS 129              // smem stride for 128-wide rows

// Scratch (static __device__ — no runtime allocation allowed)
__device__ float g_q0[(size_t)ROWS * D];
__device__ float g_k0[(size_t)ROWS * D];
__device__ float g_fq[(size_t)ROWS * F];
__device__ float g_fk[(size_t)ROWS * F];
__device__ float g_S [HEADS * F];

// ---------------------------------------------------------------------------
// Kernel 1: features. 64 rows/block, 4 threads per row, 16 outputs/thread.
//   q0 = x Wq^T + bq ; k0 = x Wk^T + bk
//   fq = [exp(q0 Wmq^T + bmq), exp(-(...))] ; fk likewise
// ---------------------------------------------------------------------------
__global__ __launch_bounds__(256, 2) void feat_kernel(
    const float* __restrict__ x,
    const float* __restrict__ Wq,  const float* __restrict__ bq,
    const float* __restrict__ Wk,  const float* __restrict__ bk,
    const float* __restrict__ Wmq, const float* __restrict__ bmq,
    const float* __restrict__ Wmk, const float* __restrict__ bmk)
{
    extern __shared__ float sm[];
    float* xs = sm;              // 64*WS
    float* qs = xs + 64*WS;      // 64*WS
    float* ks = qs + 64*WS;      // 64*WS
    float* wa = ks + 64*WS;      // 64*WS (Wq, then Wmq)
    float* wb = wa + 64*WS;      // 64*WS (Wk, then Wmk)

    const int tid  = threadIdx.x;
    const int row0 = blockIdx.x * 64;

    // load x tile (64 x 64)
    {
        const float4* src = (const float4*)(x + (size_t)row0 * D);
        for (int c = tid; c < 1024; c += 256) {
            float4 v = src[c];
            float* dst = xs + (c >> 4) * WS + (c & 15) * 4;
            dst[0]=v.x; dst[1]=v.y; dst[2]=v.z; dst[3]=v.w;
        }
    }
    // load Wq, Wk
    for (int c = tid; c < 1024; c += 256) {
        float4 v = ((const float4*)Wq)[c];
        float* dst = wa + (c >> 4) * WS + (c & 15) * 4;
        dst[0]=v.x; dst[1]=v.y; dst[2]=v.z; dst[3]=v.w;
        v = ((const float4*)Wk)[c];
        dst = wb + (c >> 4) * WS + (c & 15) * 4;
        dst[0]=v.x; dst[1]=v.y; dst[2]=v.z; dst[3]=v.w;
    }
    __syncthreads();

    const int qt = tid & 3;       // output-quarter: e = qt + 4*i
    const int rl = tid >> 2;      // local row

    float aq[16], ak[16];
    #pragma unroll
    for (int i = 0; i < 16; i++) { aq[i] = 0.f; ak[i] = 0.f; }
    #pragma unroll 4
    for (int d = 0; d < 64; d++) {
        float xv = xs[rl*WS + d];
        #pragma unroll
        for (int i = 0; i < 16; i++) {
            int e = qt + 4*i;
            aq[i] += xv * wa[e*WS + d];
            ak[i] += xv * wb[e*WS + d];
        }
    }
    const size_t grow = (size_t)(row0 + rl);
    #pragma unroll
    for (int i = 0; i < 16; i++) {
        int e = qt + 4*i;
        aq[i] += bq[e]; ak[i] += bk[e];
        qs[rl*WS + e] = aq[i];
        ks[rl*WS + e] = ak[i];
        g_q0[grow*D + e] = aq[i];
        g_k0[grow*D + e] = ak[i];
    }
    __syncthreads();

    // reload weight buffers with Wmq / Wmk
    for (int c = tid; c < 1024; c += 256) {
        float4 v = ((const float4*)Wmq)[c];
        float* dst = wa + (c >> 4) * WS + (c & 15) * 4;
        dst[0]=v.x; dst[1]=v.y; dst[2]=v.z; dst[3]=v.w;
        v = ((const float4*)Wmk)[c];
        dst = wb + (c >> 4) * WS + (c & 15) * 4;
        dst[0]=v.x; dst[1]=v.y; dst[2]=v.z; dst[3]=v.w;
    }
    __syncthreads();

    float hq[16], hk[16];
    #pragma unroll
    for (int i = 0; i < 16; i++) { int e = qt + 4*i; hq[i] = bmq[e]; hk[i] = bmk[e]; }
    #pragma unroll 4
    for (int d = 0; d < 64; d++) {
        float qv = qs[rl*WS + d];
        float kv = ks[rl*WS + d];
        #pragma unroll
        for (int i = 0; i < 16; i++) {
            int e = qt + 4*i;
            hq[i] += qv * wa[e*WS + d];
            hk[i] += kv * wb[e*WS + d];
        }
    }
    #pragma unroll
    for (int i = 0; i < 16; i++) {
        int e = qt + 4*i;
        g_fq[grow*F + e]      = __expf(hq[i]);
        g_fq[grow*F + 64 + e] = __expf(-hq[i]);
        g_fk[grow*F + e]      = __expf(hk[i]);
        g_fk[grow*F + 64 + e] = __expf(-hk[i]);
    }
}

// ---------------------------------------------------------------------------
// Kernel 2: per-head key-feature sum  S[H] = sum_n fk[H][n][:]
// (factorizes the pred normalizer: rowsum_m = fq[m] . S)
// ---------------------------------------------------------------------------
__global__ void sumk_kernel()
{
    __shared__ float sred[4][128];
    const int H    = blockIdx.x;
    const int e    = threadIdx.x & 127;
    const int part = threadIdx.x >> 7;   // 0..3, each sums 512 keys
    const float* p = g_fk + ((size_t)H*SEQ + part*512) * F + e;
    float s = 0.f;
    #pragma unroll 8
    for (int n = 0; n < 512; n++) s += p[(size_t)n * F];
    sred[part][e] = s;
    __syncthreads();
    if (part == 0)
        g_S[H*F + e] = (sred[0][e] + sred[1][e]) + (sred[2][e] + sred[3][e]);
}

// ---------------------------------------------------------------------------
// Kernel 3: scores. Block = 128 m-rows of one head, streaming 128-key tiles.
// 256 threads = 16x16; each thread owns an 8x8 output tile:
//   m = ty + 16*i          (broadcast a-reads)
//   n = 4*tx + 64*jj + q   (2-way-conflict scalar b-reads, float4 stores)
//   pred = (fq.fk) * rinv[m]      (single pass, factorized normalizer)
//   true = exp(q0.k0/8) raw, then block-local L2-hot rescale by 1/sumexp
// ---------------------------------------------------------------------------
__global__ __launch_bounds__(256, 1) void attn_kernel(float* __restrict__ out)
{
    extern __shared__ float sm[];
    float* fq_s = sm;                   // 128*FS
    float* fk_s = fq_s + 128*FS;        // 128*FS
    float* q0_s = fk_s + 128*FS;        // 128*WS
    float* k0_s = q0_s + 128*WS;        // 128*WS
    float* rinv = k0_s + 128*WS;        // 128
    float* sinv = rinv + 128;           // 128
    float* red  = sinv + 128;           // 128*16

    const int tid = threadIdx.x;
    const int tx  = tid & 15;
    const int ty  = tid >> 4;
    const int H   = blockIdx.y;
    const int m0  = blockIdx.x * 128;
    const size_t headrow  = (size_t)H * SEQ;
    const size_t TRUE_OFF = (size_t)HEADS * SEQ * SEQ;   // 134217728

    // load persistent fq / q0 tiles (rows m0..m0+127)
    {
        const float4* src = (const float4*)(g_fq + (headrow + m0) * F);
        for (int c = tid; c < 4096; c += 256) {
            float4 v = src[c];
            float* dst = fq_s + (c >> 5)*FS + (c & 31)*4;
            dst[0]=v.x; dst[1]=v.y; dst[2]=v.z; dst[3]=v.w;
        }
        const float4* qsrc = (const float4*)(g_q0 + (headrow + m0) * D);
        for (int c = tid; c < 2048; c += 256) {
            float4 v = qsrc[c];
            float* dst = q0_s + (c >> 4)*WS + (c & 15)*4;
            dst[0]=v.x; dst[1]=v.y; dst[2]=v.z; dst[3]=v.w;
        }
    }
    __syncthreads();
    if (tid < 128) {
        const float* Sv = g_S + H*F;
        float s = 0.f;
        #pragma unroll 4
        for (int d = 0; d < F; d++) s += fq_s[tid*FS + d] * Sv[d];
        rinv[tid] = 1.0f / s;
    }

    float sacc[8];
    #pragma unroll
    for (int i = 0; i < 8; i++) sacc[i] = 0.f;

    float* predb = out + (headrow + m0) * SEQ;
    float* trueb = out + TRUE_OFF + (headrow + m0) * SEQ;

    for (int nt = 0; nt < 16; nt++) {
        const int n0 = nt * 128;
        __syncthreads();   // prev-tile consumers done (also orders rinv on iter 0)

        // stream fk / k0 key tile (rows n0..n0+127)
        {
            const float4* fsrc = (const float4*)(g_fk + (headrow + n0) * F);
            for (int c = tid; c < 4096; c += 256) {
                float4 v = fsrc[c];
                float* dst = fk_s + (c >> 5)*FS + (c & 31)*4;
                dst[0]=v.x; dst[1]=v.y; dst[2]=v.z; dst[3]=v.w;
            }
            const float4* ksrc = (const float4*)(g_k0 + (headrow + n0) * D);
            for (int c = tid; c < 2048; c += 256) {
                float4 v = ksrc[c];
                float* dst = k0_s + (c >> 4)*WS + (c & 15)*4;
                dst[0]=v.x; dst[1]=v.y; dst[2]=v.z; dst[3]=v.w;
            }
        }
        __syncthreads();

        // ---- pred: fq . fk over F=128 ----
        {
            float acc[8][8];
            #pragma unroll
            for (int i = 0; i < 8; i++)
                #pragma unroll
                for (int j = 0; j < 8; j++) acc[i][j] = 0.f;

            #pragma unroll 4
            for (int d = 0; d < F; d++) {
                float a[8], b[8];
                #pragma unroll
                for (int i = 0; i < 8; i++) a[i] = fq_s[(ty + 16*i)*FS + d];
                #pragma unroll
                for (int jj = 0; jj < 2; jj++)
                    #pragma unroll
                    for (int q = 0; q < 4; q++)
                        b[jj*4+q] = fk_s[(4*tx + 64*jj + q)*FS + d];
                #pragma unroll
                for (int i = 0; i < 8; i++)
                    #pragma unroll
                    for (int j = 0; j < 8; j++)
                        acc[i][j] += a[i] * b[j];
            }
            #pragma unroll
            for (int i = 0; i < 8; i++) {
                const int ml = ty + 16*i;
                const float r = rinv[ml];
                #pragma unroll
                for (int jj = 0; jj < 2; jj++) {
                    float4 w;
                    w.x = acc[i][jj*4+0]*r; w.y = acc[i][jj*4+1]*r;
                    w.z = acc[i][jj*4+2]*r; w.w = acc[i][jj*4+3]*r;
                    *(float4*)(predb + (size_t)ml*SEQ + n0 + 4*tx + 64*jj) = w;
                }
            }
        }

        // ---- true: exp(q0 . k0 / 8) over D=64, raw + running row-sum ----
        {
            float sc[8][8];
            #pragma unroll
            for (int i = 0; i < 8; i++)
                #pragma unroll
                for (int j = 0; j < 8; j++) sc[i][j] = 0.f;

            #pragma unroll 4
            for (int d = 0; d < D; d++) {
                float a[8], b[8];
                #pragma unroll
                for (int i = 0; i < 8; i++) a[i] = q0_s[(ty + 16*i)*WS + d];
                #pragma unroll
                for (int jj = 0; jj < 2; jj++)
                    #pragma unroll
                    for (int q = 0; q < 4; q++)
                        b[jj*4+q] = k0_s[(4*tx + 64*jj + q)*WS + d];
                #pragma unroll
                for (int i = 0; i < 8; i++)
                    #pragma unroll
                    for (int j = 0; j < 8; j++)
                        sc[i][j] += a[i] * b[j];
            }
            #pragma unroll
            for (int i = 0; i < 8; i++) {
                const int ml = ty + 16*i;
                #pragma unroll
                for (int jj = 0; jj < 2; jj++) {
                    float e0 = __expf(sc[i][jj*4+0]*0.125f);
                    float e1 = __expf(sc[i][jj*4+1]*0.125f);
                    float e2 = __expf(sc[i][jj*4+2]*0.125f);
                    float e3 = __expf(sc[i][jj*4+3]*0.125f);
                    sacc[i] += (e0 + e1) + (e2 + e3);
                    float4 w; w.x=e0; w.y=e1; w.z=e2; w.w=e3;
                    *(float4*)(trueb + (size_t)ml*SEQ + n0 + 4*tx + 64*jj) = w;
                }
            }
        }
    }

    // reduce per-row sumexp across tx, then rescale our (L2-hot) true rows
    __syncthreads();
    #pragma unroll
    for (int i = 0; i < 8; i++) red[(ty + 16*i)*16 + tx] = sacc[i];
    __syncthreads();
    if (tid < 128) {
        float s = 0.f;
        #pragma unroll
        for (int k = 0; k < 16; k++) s += red[tid*16 + k];
        sinv[tid] = 1.0f / s;
    }
    __syncthreads();   // also orders the block's global stores for re-read

    float4* tb4 = (float4*)trueb;
    for (int c = tid; c < 128*512; c += 256) {   // 128 rows x 512 float4
        int r = c >> 9;
        float f = sinv[r];
        float4 v = tb4[c];
        v.x *= f; v.y *= f; v.z *= f; v.w *= f;
        tb4[c] = v;
    }
}

// ---------------------------------------------------------------------------
extern "C" void kernel_launch(void* const* d_in, const int* in_sizes, int n_in,
                              void* d_out, int out_size)
{
    const float* x   = (const float*)d_in[0];
    const float* Wq  = (const float*)d_in[1];
    const float* bq  = (const float*)d_in[2];
    const float* Wk  = (const float*)d_in[3];
    const float* bk  = (const float*)d_in[4];
    const float* Wmq = (const float*)d_in[5];
    const float* bmq = (const float*)d_in[6];
    const float* Wmk = (const float*)d_in[7];
    const float* bmk = (const float*)d_in[8];
    float* out = (float*)d_out;

    const int SM1 = 5 * 64 * WS * (int)sizeof(float);                          // 83.2 KB
    const int SM2 = (2*128*FS + 2*128*WS + 128 + 128 + 128*16) * (int)sizeof(float); // 207.9 KB

    cudaFuncSetAttribute(feat_kernel, cudaFuncAttributeMaxDynamicSharedMemorySize, SM1);
    cudaFuncSetAttribute(attn_kernel, cudaFuncAttributeMaxDynamicSharedMemorySize, SM2);

    feat_kernel<<<ROWS / 64, 256, SM1>>>(x, Wq, bq, Wk, bk, Wmq, bmq, Wmk, bmk);
    sumk_kernel<<<HEADS, 512>>>();
    attn_kernel<<<dim3(SEQ / 128, HEADS), 256, SM2>>>(out);
}

// round 15
// speedup vs baseline: 1.8572x; 1.8572x over previous
#include <cuda_runtime.h>
#include <cuda_bf16.h>
#include <cstdint>

#define HEADS 32
#define SEQ   2048
#define D     64
#define F     128
#define ROWS  (HEADS*SEQ)   // 65536

#define WS 65               // feat smem stride

// ---------------- global scratch (static, no runtime alloc) ----------------
__device__ __nv_bfloat16 g_q0h[(size_t)ROWS * D];
__device__ __nv_bfloat16 g_q0l[(size_t)ROWS * D];
__device__ __nv_bfloat16 g_k0h[(size_t)ROWS * D];
__device__ __nv_bfloat16 g_k0l[(size_t)ROWS * D];
__device__ __nv_bfloat16 g_fqh[(size_t)ROWS * F];
__device__ __nv_bfloat16 g_fql[(size_t)ROWS * F];
__device__ __nv_bfloat16 g_fkh[(size_t)ROWS * F];
__device__ __nv_bfloat16 g_fkl[(size_t)ROWS * F];
__device__ float g_S   [HEADS * F];
__device__ float g_rinv[ROWS];

// ---------------- helpers ----------------
__device__ __forceinline__ uint32_t smem_u32(const void* p) {
    uint32_t a;
    asm("{ .reg .u64 t; cvta.to.shared.u64 t, %1; cvt.u32.u64 %0, t; }" : "=r"(a) : "l"(p));
    return a;
}
__device__ __forceinline__ void ldsm4(uint32_t* r, uint32_t addr) {
    asm volatile("ldmatrix.sync.aligned.m8n8.x4.shared.b16 {%0,%1,%2,%3}, [%4];"
                 : "=r"(r[0]), "=r"(r[1]), "=r"(r[2]), "=r"(r[3]) : "r"(addr));
}
__device__ __forceinline__ void mma16816(float* c, const uint32_t* a, uint32_t b0, uint32_t b1) {
    asm volatile(
        "mma.sync.aligned.m16n8k16.row.col.f32.bf16.bf16.f32 "
        "{%0,%1,%2,%3}, {%4,%5,%6,%7}, {%8,%9}, {%0,%1,%2,%3};"
        : "+f"(c[0]), "+f"(c[1]), "+f"(c[2]), "+f"(c[3])
        : "r"(a[0]), "r"(a[1]), "r"(a[2]), "r"(a[3]), "r"(b0), "r"(b1));
}

// pack 8 fp32 -> 8 bf16 hi + 8 bf16 lo, 16B stores
__device__ __forceinline__ void store_hilo8(const float* v, __nv_bfloat16* gh, __nv_bfloat16* gl) {
    __nv_bfloat162 h[4], l[4];
    #pragma unroll
    for (int i = 0; i < 4; i++) {
        float a = v[2*i], b = v[2*i+1];
        __nv_bfloat16 ha = __float2bfloat16(a), hb = __float2bfloat16(b);
        float la = a - __bfloat162float(ha), lb = b - __bfloat162float(hb);
        h[i] = __halves2bfloat162(ha, hb);
        l[i] = __halves2bfloat162(__float2bfloat16(la), __float2bfloat16(lb));
    }
    *(uint4*)gh = *(const uint4*)h;
    *(uint4*)gl = *(const uint4*)l;
}

// ---------------------------------------------------------------------------
// Kernel 1: features (projections + hedgehog exp), emits bf16 hi/lo splits.
// ---------------------------------------------------------------------------
__global__ __launch_bounds__(256, 2) void feat_kernel(
    const float* __restrict__ x,
    const float* __restrict__ Wq,  const float* __restrict__ bq,
    const float* __restrict__ Wk,  const float* __restrict__ bk,
    const float* __restrict__ Wmq, const float* __restrict__ bmq,
    const float* __restrict__ Wmk, const float* __restrict__ bmk)
{
    extern __shared__ float sm[];
    float* xs = sm;
    float* qs = xs + 64*WS;
    float* ks = qs + 64*WS;
    float* wa = ks + 64*WS;
    float* wb = wa + 64*WS;

    const int tid  = threadIdx.x;
    const int row0 = blockIdx.x * 64;

    {
        const float4* src = (const float4*)(x + (size_t)row0 * D);
        for (int c = tid; c < 1024; c += 256) {
            float4 v = src[c];
            float* dst = xs + (c >> 4) * WS + (c & 15) * 4;
            dst[0]=v.x; dst[1]=v.y; dst[2]=v.z; dst[3]=v.w;
        }
    }
    for (int c = tid; c < 1024; c += 256) {
        float4 v = ((const float4*)Wq)[c];
        float* dst = wa + (c >> 4) * WS + (c & 15) * 4;
        dst[0]=v.x; dst[1]=v.y; dst[2]=v.z; dst[3]=v.w;
        v = ((const float4*)Wk)[c];
        dst = wb + (c >> 4) * WS + (c & 15) * 4;
        dst[0]=v.x; dst[1]=v.y; dst[2]=v.z; dst[3]=v.w;
    }
    __syncthreads();

    const int qt = tid & 3;
    const int rl = tid >> 2;

    float aq[16], ak[16];
    #pragma unroll
    for (int i = 0; i < 16; i++) { aq[i] = 0.f; ak[i] = 0.f; }
    #pragma unroll 4
    for (int d = 0; d < 64; d++) {
        float xv = xs[rl*WS + d];
        #pragma unroll
        for (int i = 0; i < 16; i++) {
            int e = qt + 4*i;
            aq[i] += xv * wa[e*WS + d];
            ak[i] += xv * wb[e*WS + d];
        }
    }
    #pragma unroll
    for (int i = 0; i < 16; i++) {
        int e = qt + 4*i;
        aq[i] += bq[e]; ak[i] += bk[e];
        qs[rl*WS + e] = aq[i];
        ks[rl*WS + e] = ak[i];
    }
    __syncthreads();

    for (int c = tid; c < 512; c += 256) {
        int r = c >> 3, g8 = (c & 7) * 8;
        size_t go = (size_t)(row0 + r) * D + g8;
        store_hilo8(qs + r*WS + g8, g_q0h + go, g_q0l + go);
        store_hilo8(ks + r*WS + g8, g_k0h + go, g_k0l + go);
    }
    for (int c = tid; c < 1024; c += 256) {
        float4 v = ((const float4*)Wmq)[c];
        float* dst = wa + (c >> 4) * WS + (c & 15) * 4;
        dst[0]=v.x; dst[1]=v.y; dst[2]=v.z; dst[3]=v.w;
        v = ((const float4*)Wmk)[c];
        dst = wb + (c >> 4) * WS + (c & 15) * 4;
        dst[0]=v.x; dst[1]=v.y; dst[2]=v.z; dst[3]=v.w;
    }
    __syncthreads();

    float hq[16], hk[16];
    #pragma unroll
    for (int i = 0; i < 16; i++) { int e = qt + 4*i; hq[i] = bmq[e]; hk[i] = bmk[e]; }
    #pragma unroll 4
    for (int d = 0; d < 64; d++) {
        float qv = qs[rl*WS + d];
        float kv = ks[rl*WS + d];
        #pragma unroll
        for (int i = 0; i < 16; i++) {
            int e = qt + 4*i;
            hq[i] += qv * wa[e*WS + d];
            hk[i] += kv * wb[e*WS + d];
        }
    }
    __syncthreads();

    #pragma unroll
    for (int i = 0; i < 16; i++) {
        int e = qt + 4*i;
        xs[rl*WS + e] = __expf(hq[i]);
        qs[rl*WS + e] = __expf(-hq[i]);
        ks[rl*WS + e] = __expf(hk[i]);
        wa[rl*WS + e] = __expf(-hk[i]);
    }
    __syncthreads();

    for (int c = tid; c < 512; c += 256) {
        int r = c >> 3, g8 = (c & 7) * 8;
        size_t go = (size_t)(row0 + r) * F;
        store_hilo8(xs + r*WS + g8, g_fqh + go + g8,      g_fql + go + g8);
        store_hilo8(qs + r*WS + g8, g_fqh + go + 64 + g8, g_fql + go + 64 + g8);
        store_hilo8(ks + r*WS + g8, g_fkh + go + g8,      g_fkl + go + g8);
        store_hilo8(wa + r*WS + g8, g_fkh + go + 64 + g8, g_fkl + go + 64 + g8);
    }
}

// ---------------------------------------------------------------------------
// Kernel 2: per-head key-feature sum S[H] = sum_n fk[n] (hi+lo)
// ---------------------------------------------------------------------------
__global__ void sumk_kernel()
{
    __shared__ float sred[4][128];
    const int H    = blockIdx.x;
    const int e    = threadIdx.x & 127;
    const int part = threadIdx.x >> 7;
    const __nv_bfloat16* ph = g_fkh + ((size_t)H*SEQ + part*512) * F + e;
    const __nv_bfloat16* pl = g_fkl + ((size_t)H*SEQ + part*512) * F + e;
    float s = 0.f;
    #pragma unroll 8
    for (int n = 0; n < 512; n++)
        s += __bfloat162float(ph[(size_t)n*F]) + __bfloat162float(pl[(size_t)n*F]);
    sred[part][e] = s;
    __syncthreads();
    if (part == 0)
        g_S[H*F + e] = (sred[0][e] + sred[1][e]) + (sred[2][e] + sred[3][e]);
}

// ---------------------------------------------------------------------------
// Kernel 2b: rinv[row] = 1 / (fq[row] . S[head])
// ---------------------------------------------------------------------------
__global__ void rinv_kernel()
{
    const int w = threadIdx.x >> 5, lane = threadIdx.x & 31;
    const int row = blockIdx.x * 8 + w;
    const int H = row >> 11;
    const __nv_bfloat16* ph = g_fqh + (size_t)row * F;
    const __nv_bfloat16* pl = g_fql + (size_t)row * F;
    const float* S = g_S + H * F;
    float s = 0.f;
    #pragma unroll
    for (int i = 0; i < 4; i++) {
        int d = lane + 32*i;
        s += (__bfloat162float(ph[d]) + __bfloat162float(pl[d])) * S[d];
    }
    #pragma unroll
    for (int o = 16; o; o >>= 1) s += __shfl_xor_sync(0xffffffffu, s, o);
    if (lane == 0) g_rinv[row] = 1.0f / s;
}

// ---------------------------------------------------------------------------
// Kernel 3: warp-MMA split-bf16 score kernel (base-ISA mma.sync, no tcgen05).
// Block = (head H, 128 m-rows), streams 128-key tiles.
// 8 warps = 2(m) x 4(n); each warp computes 64x32 via 4x4 m16n8k16 tiles.
//   pred = (Fqh*Fkh + Fqh*Fkl + Fql*Fkh) * rinv[m]     (K=128 per product)
//   true = exp((Q0h*K0h + Q0h*K0l + Q0l*K0h)/8), raw + block rescale (K=64)
// smem rows padded: 128-half rows -> 272B stride, 64-half rows -> 144B stride
// (16B row shift mod 128 -> conflict-free ldmatrix).
// ---------------------------------------------------------------------------
#define FQH_O  0u
#define FQL_O  34816u
#define Q0H_O  69632u
#define Q0L_O  88064u
#define FKH_O  106496u
#define FKL_O  141312u
#define K0H_O  176128u
#define K0L_O  194560u
#define RINV_O 212992u
#define RED_O  213504u
#define SINV_O 215552u
#define SM_ATTN 216064

// 128 rows x 128 halves, dst stride 272B
__device__ __forceinline__ void copyF(char* smem, uint32_t off,
                                      const __nv_bfloat16* __restrict__ g,
                                      size_t grow0, int tid)
{
    #pragma unroll
    for (int it = 0; it < 8; it++) {
        int c = tid + it * 256;
        int r = c >> 4, u = c & 15;
        *(uint4*)(smem + off + r*272 + u*16) = *(const uint4*)(g + (grow0 + r)*F + u*8);
    }
}
// 128 rows x 64 halves, dst stride 144B
__device__ __forceinline__ void copyD(char* smem, uint32_t off,
                                      const __nv_bfloat16* __restrict__ g,
                                      size_t grow0, int tid)
{
    #pragma unroll
    for (int it = 0; it < 4; it++) {
        int c = tid + it * 256;
        int r = c >> 3, u = c & 7;
        *(uint4*)(smem + off + r*144 + u*16) = *(const uint4*)(g + (grow0 + r)*D + u*8);
    }
}

__global__ __launch_bounds__(256, 1) void attn_kernel(float* __restrict__ out)
{
    extern __shared__ char smem[];
    const uint32_t sb = smem_u32(smem);

    const int tid  = threadIdx.x;
    const int lane = tid & 31;
    const int w    = tid >> 5;
    const int wm   = w >> 2;          // 0/1 : m half
    const int wn   = w & 3;           // 0..3: n quarter
    const int H    = blockIdx.y;
    const int m0   = blockIdx.x * 128;
    const size_t headrow  = (size_t)H * SEQ;
    const size_t TRUE_OFF = (size_t)HEADS * SEQ * SEQ;

    // ldmatrix lane->row/k mapping
    const int a_row = (lane & 7) | (lane & 8);            // 0..15
    const int a_kB  = ((lane >> 4) * 8) * 2;              // byte offset in k
    const int b_row = (lane & 7) + ((lane >> 1) & 8);     // 0..15
    const int b_kB  = (((lane >> 3) & 1) * 8) * 2;

    // persistent A tiles (fq hi/lo, q0 hi/lo for rows m0..m0+127)
    copyF(smem, FQH_O, g_fqh, headrow + m0, tid);
    copyF(smem, FQL_O, g_fql, headrow + m0, tid);
    copyD(smem, Q0H_O, g_q0h, headrow + m0, tid);
    copyD(smem, Q0L_O, g_q0l, headrow + m0, tid);
    if (tid < 128)
        *(float*)(smem + RINV_O + 4u*tid) = g_rinv[headrow + m0 + tid];
    __syncthreads();

    float* rinv_s = (float*)(smem + RINV_O);
    float* red_s  = (float*)(smem + RED_O);
    float* sinv_s = (float*)(smem + SINV_O);

    float sacc0[4], sacc1[4];
    #pragma unroll
    for (int i = 0; i < 4; i++) { sacc0[i] = 0.f; sacc1[i] = 0.f; }

    float* predb = out + (headrow + m0) * SEQ;
    float* trueb = out + TRUE_OFF + (headrow + m0) * SEQ;

    const int colb = (lane & 3) * 2;     // col offset within n8 tile
    const int rquad = lane >> 2;         // 0..7 row-within-16-tile

    for (int nt = 0; nt < 16; nt++) {
        const int n0 = nt * 128;
        __syncthreads();   // previous-iteration consumers done

        copyF(smem, FKH_O, g_fkh, headrow + n0, tid);
        copyF(smem, FKL_O, g_fkl, headrow + n0, tid);
        copyD(smem, K0H_O, g_k0h, headrow + n0, tid);
        copyD(smem, K0L_O, g_k0l, headrow + n0, tid);
        __syncthreads();

        // ================= pred GEMM: K=128, 3 products =================
        {
            float cp[4][4][4];
            #pragma unroll
            for (int i = 0; i < 4; i++)
                #pragma unroll
                for (int j = 0; j < 4; j++)
                    #pragma unroll
                    for (int q = 0; q < 4; q++) cp[i][j][q] = 0.f;

            const uint32_t aoff[3] = {FQH_O, FQH_O, FQL_O};
            const uint32_t boff[3] = {FKH_O, FKL_O, FKH_O};
            #pragma unroll
            for (int p = 0; p < 3; p++) {
                const uint32_t abase = sb + aoff[p] + (wm*64 + a_row)*272 + a_kB;
                const uint32_t bbase = sb + boff[p] + (wn*32 + b_row)*272 + b_kB;
                #pragma unroll
                for (int k = 0; k < 128; k += 16) {
                    uint32_t A[4][4], B[2][4];
                    #pragma unroll
                    for (int i = 0; i < 4; i++) ldsm4(A[i], abase + i*16*272 + k*2);
                    #pragma unroll
                    for (int jj = 0; jj < 2; jj++) ldsm4(B[jj], bbase + jj*16*272 + k*2);
                    #pragma unroll
                    for (int i = 0; i < 4; i++)
                        #pragma unroll
                        for (int jj = 0; jj < 2; jj++) {
                            mma16816(cp[i][2*jj],   A[i], B[jj][0], B[jj][1]);
                            mma16816(cp[i][2*jj+1], A[i], B[jj][2], B[jj][3]);
                        }
                }
            }
            // epilogue: scale by rinv, store float2 pairs (quad -> 32B sectors)
            #pragma unroll
            for (int i = 0; i < 4; i++) {
                const int r0 = wm*64 + i*16 + rquad;
                const float rv0 = rinv_s[r0], rv1 = rinv_s[r0 + 8];
                float* row0 = predb + (size_t)r0 * SEQ + n0 + wn*32 + colb;
                #pragma unroll
                for (int j = 0; j < 4; j++) {
                    float2 v0 = make_float2(cp[i][j][0]*rv0, cp[i][j][1]*rv0);
                    float2 v1 = make_float2(cp[i][j][2]*rv1, cp[i][j][3]*rv1);
                    *(float2*)(row0 + j*8)           = v0;
                    *(float2*)(row0 + 8*SEQ + j*8)   = v1;
                }
            }
        }

        // ================= true GEMM: K=64, 3 products ==================
        {
            float ct[4][4][4];
            #pragma unroll
            for (int i = 0; i < 4; i++)
                #pragma unroll
                for (int j = 0; j < 4; j++)
                    #pragma unroll
                    for (int q = 0; q < 4; q++) ct[i][j][q] = 0.f;

            const uint32_t aoff[3] = {Q0H_O, Q0H_O, Q0L_O};
            const uint32_t boff[3] = {K0H_O, K0L_O, K0H_O};
            #pragma unroll
            for (int p = 0; p < 3; p++) {
                const uint32_t abase = sb + aoff[p] + (wm*64 + a_row)*144 + a_kB;
                const uint32_t bbase = sb + boff[p] + (wn*32 + b_row)*144 + b_kB;
                #pragma unroll
                for (int k = 0; k < 64; k += 16) {
                    uint32_t A[4][4], B[2][4];
                    #pragma unroll
                    for (int i = 0; i < 4; i++) ldsm4(A[i], abase + i*16*144 + k*2);
                    #pragma unroll
                    for (int jj = 0; jj < 2; jj++) ldsm4(B[jj], bbase + jj*16*144 + k*2);
                    #pragma unroll
                    for (int i = 0; i < 4; i++)
                        #pragma unroll
                        for (int jj = 0; jj < 2; jj++) {
                            mma16816(ct[i][2*jj],   A[i], B[jj][0], B[jj][1]);
                            mma16816(ct[i][2*jj+1], A[i], B[jj][2], B[jj][3]);
                        }
                }
            }
            // epilogue: raw exp(score/8) + running per-row sums
            #pragma unroll
            for (int i = 0; i < 4; i++) {
                const int r0 = wm*64 + i*16 + rquad;
                float* row0 = trueb + (size_t)r0 * SEQ + n0 + wn*32 + colb;
                float s0 = 0.f, s1 = 0.f;
                #pragma unroll
                for (int j = 0; j < 4; j++) {
                    float e0 = __expf(ct[i][j][0]*0.125f);
                    float e1 = __expf(ct[i][j][1]*0.125f);
                    float e2 = __expf(ct[i][j][2]*0.125f);
                    float e3 = __expf(ct[i][j][3]*0.125f);
                    s0 += e0 + e1; s1 += e2 + e3;
                    *(float2*)(row0 + j*8)         = make_float2(e0, e1);
                    *(float2*)(row0 + 8*SEQ + j*8) = make_float2(e2, e3);
                }
                sacc0[i] += s0; sacc1[i] += s1;
            }
        }
    }

    // reduce row sums: quad lanes share a row; 4 n-warps share rows via red_s
    #pragma unroll
    for (int i = 0; i < 4; i++) {
        float s0 = sacc0[i], s1 = sacc1[i];
        s0 += __shfl_xor_sync(0xffffffffu, s0, 1);
        s0 += __shfl_xor_sync(0xffffffffu, s0, 2);
        s1 += __shfl_xor_sync(0xffffffffu, s1, 1);
        s1 += __shfl_xor_sync(0xffffffffu, s1, 2);
        if ((lane & 3) == 0) {
            const int r0 = wm*64 + i*16 + rquad;
            red_s[r0*4 + wn]       = s0;
            red_s[(r0 + 8)*4 + wn] = s1;
        }
    }
    __syncthreads();
    if (tid < 128)
        sinv_s[tid] = 1.0f / (red_s[4*tid] + red_s[4*tid+1] + red_s[4*tid+2] + red_s[4*tid+3]);
    __syncthreads();

    // rescale our (L2-hot) true rows
    float4* tb4 = (float4*)trueb;
    for (int c = tid; c < 128*512; c += 256) {
        int rr = c >> 9;
        float f = sinv_s[rr];
        float4 v = tb4[c];
        v.x *= f; v.y *= f; v.z *= f; v.w *= f;
        tb4[c] = v;
    }
}

// ---------------------------------------------------------------------------
extern "C" void kernel_launch(void* const* d_in, const int* in_sizes, int n_in,
                              void* d_out, int out_size)
{
    const float* x   = (const float*)d_in[0];
    const float* Wq  = (const float*)d_in[1];
    const float* bq  = (const float*)d_in[2];
    const float* Wk  = (const float*)d_in[3];
    const float* bk  = (const float*)d_in[4];
    const float* Wmq = (const float*)d_in[5];
    const float* bmq = (const float*)d_in[6];
    const float* Wmk = (const float*)d_in[7];
    const float* bmk = (const float*)d_in[8];
    float* out = (float*)d_out;

    const int SM1 = 5 * 64 * WS * (int)sizeof(float);   // 83.2 KB

    cudaFuncSetAttribute(feat_kernel, cudaFuncAttributeMaxDynamicSharedMemorySize, SM1);
    cudaFuncSetAttribute(attn_kernel, cudaFuncAttributeMaxDynamicSharedMemorySize, SM_ATTN);

    feat_kernel<<<ROWS / 64, 256, SM1>>>(x, Wq, bq, Wk, bk, Wmq, bmq, Wmk, bmk);
    sumk_kernel<<<HEADS, 512>>>();
    rinv_kernel<<<ROWS / 8, 256>>>();
    attn_kernel<<<dim3(SEQ / 128, HEADS), 256, SM_ATTN>>>(out);
}